// round 5
// baseline (speedup 1.0000x reference)
#include <cuda_runtime.h>
#include <cuda_bf16.h>
#include <cstdint>

// ---------------- problem constants ----------------
#define B_    2
#define N_    262144
#define T_    122                     // valid output points per CTA
#define ROWS_ 128                     // buffer rows (halo 3 each side)
#define NTILE ((N_ + T_ - 1) / T_)    // 2149
#define EPS_  1e-5f

// ---------------- smem layout (bytes) ----------------
// 4 activation buffers (ping-pong pairs x {hi,lo}) of 128 rows x 144B
// bias: 3 x 64 floats. NO weight smem: fragments stream via LDG/L1.
#define ROWSTRIDE 144
#define BUFBYTES  (ROWS_ * ROWSTRIDE)      // 18432
#define SM_BUF    0
#define SM_BIAS   (4 * BUFBYTES)           // 73728
#define SM_TOTAL  (SM_BIAS + 768)          // 74496  -> 2 CTAs/SM

// ---------------- device globals (no allocs allowed) ----------------
__device__ float   g_tmp[(size_t)B_ * N_ * 64];     // inter-block scratch (128 MB)
__device__ __align__(16) uint32_t g_wfrag[73728];   // [bk][L][t][part][nb][kb][lane][reg]
__device__ float   g_bias[2][192];                  // folded bias [blk][L*64+o]
__device__ int     g_idx64;

// ---------------- helpers ----------------
__device__ __forceinline__ uint32_t smem_u32(const void* p) {
    uint32_t a;
    asm("{ .reg .u64 t; cvta.to.shared.u64 t, %1; cvt.u32.u64 %0, t; }" : "=r"(a) : "l"(p));
    return a;
}
__device__ __forceinline__ uint16_t f2bf(float f) {
    __nv_bfloat16 h = __float2bfloat16_rn(f);
    return *(uint16_t*)&h;
}
__device__ __forceinline__ float bf2f(uint32_t u) {  // low 16 bits = bf16 pattern
    return __uint_as_float((u & 0xFFFFu) << 16);
}
// pack (v0,v1) -> {hi bf16x2, lo bf16x2} with v0 in the low half
__device__ __forceinline__ uint2 pack2(float v0, float v1) {
    uint32_t h;
    asm("cvt.rn.bf16x2.f32 %0, %1, %2;" : "=r"(h) : "f"(v1), "f"(v0));
    float l0 = v0 - __uint_as_float(h << 16);
    float l1 = v1 - __uint_as_float(h & 0xFFFF0000u);
    uint32_t l;
    asm("cvt.rn.bf16x2.f32 %0, %1, %2;" : "=r"(l) : "f"(l1), "f"(l0));
    return make_uint2(h, l);
}

__device__ __forceinline__ void mma_bf16(float d[4], const uint32_t a[4],
                                         uint32_t b0, uint32_t b1) {
    asm volatile(
        "mma.sync.aligned.m16n8k16.row.col.f32.bf16.bf16.f32 "
        "{%0,%1,%2,%3}, {%4,%5,%6,%7}, {%8,%9}, {%0,%1,%2,%3};"
        : "+f"(d[0]), "+f"(d[1]), "+f"(d[2]), "+f"(d[3])
        : "r"(a[0]), "r"(a[1]), "r"(a[2]), "r"(a[3]), "r"(b0), "r"(b1));
}

#define LDSM4(a, addr)                                                         \
    asm volatile("ldmatrix.sync.aligned.m8n8.x4.shared.b16 {%0,%1,%2,%3}, [%4];" \
        : "=r"((a)[0]), "=r"((a)[1]), "=r"((a)[2]), "=r"((a)[3]) : "r"(addr))

// ---------------------------------------------------------------------------
// Prep: fold BN into conv weights, split bf16 hi/lo, emit mma.sync B-fragments
// in final lane/register layout; fold bias; detect index dtype.
// ---------------------------------------------------------------------------
__global__ void prep_kernel(const float* __restrict__ conv_w,
                            const float* __restrict__ bg,
                            const float* __restrict__ bb,
                            const float* __restrict__ bm,
                            const float* __restrict__ bv,
                            const void*  __restrict__ pa1)
{
    int idx = blockIdx.x * blockDim.x + threadIdx.x;

    if (idx == 0) {
        const int* p = (const int*)pa1;   // int64 perm -> zero high words
        g_idx64 = (p[1] == 0 && p[3] == 0 && p[5] == 0 && p[7] == 0) ? 1 : 0;
    }
    if (idx < 384) {                      // bias fold [bk][L][o]
        int o = idx & 63, L = (idx >> 6) % 3, bk = idx / 192;
        float sc = bg[idx] * rsqrtf(bv[idx] + EPS_);
        g_bias[bk][L * 64 + o] = bb[idx] - bm[idx] * sc;
    }
    if (idx < 73728) {
        int q = idx;
        int reg  = q & 1;  q >>= 1;
        int lane = q & 31; q >>= 5;
        int kb   = q & 3;  q >>= 2;
        int nb   = q & 7;  q >>= 3;
        int part = q & 1;  q >>= 1;
        int t    = q % 3;  q /= 3;
        int L    = q % 3;
        int bk   = q / 3;

        int n  = nb * 8 + (lane >> 2);                 // output channel
        int k0 = kb * 16 + reg * 8 + (lane & 3) * 2;   // input channel pair
        int bni = (bk * 3 + L) * 64 + n;
        float sc = bg[bni] * rsqrtf(bv[bni] + EPS_);

        uint16_t hv[2];
        #pragma unroll
        for (int h = 0; h < 2; ++h) {
            int i = k0 + h;
            float w = conv_w[(((size_t)(bk * 3 + L) * 64 + n) * 64 + i) * 3 + t] * sc;
            uint16_t hi = f2bf(w);
            hv[h] = (part == 0) ? hi : f2bf(w - bf2f(hi));
        }
        g_wfrag[idx] = (uint32_t)hv[0] | ((uint32_t)hv[1] << 16);
    }
}

// ---------------------------------------------------------------------------
// Fused block: gather -> 3 x (mma.sync conv + BN + act) -> residual -> scatter
// One CTA = 122 output points (128-row buffer), 128 threads (4 warps x M=32),
// 2 CTAs/SM. Weight fragments stream via LDG (L1-resident, 48KB/layer).
// ---------------------------------------------------------------------------
__global__ void __launch_bounds__(128, 2)
mc_block_kernel(const float* __restrict__ xin,
                const void*  __restrict__ pav,
                float* __restrict__ out,
                int bk)
{
    extern __shared__ uint8_t smem[];
    const uint32_t sbase = smem_u32(smem);
    const int tid = threadIdx.x, wid = tid >> 5, lane = tid & 31;
    const int b = blockIdx.y;
    const int ts = blockIdx.x * T_;
    const bool is64 = (g_idx64 != 0);
    const int*       pa32 = (const int*)pav;
    const long long* pa64 = (const long long*)pav;

    #pragma unroll
    for (int i = tid; i < 192; i += 128)
        ((float*)(smem + SM_BIAS))[i] = g_bias[bk][i];

    // ---- gather 128 rows (points ts-3 .. ts+124), bf16 hi/lo split ----
    {
        const int r = tid;                 // one thread per row
        int gp = ts - 3 + r;
        bool ok = (gp >= 0) && (gp < N_);
        const float4* src = nullptr;
        if (ok) {
            long long prow = is64 ? pa64[(size_t)b * N_ + gp]
                                  : (long long)pa32[(size_t)b * N_ + gp];
            src = (const float4*)(xin + ((size_t)b * N_ + (size_t)prow) * 64);
        }
        uint8_t* bh0 = smem + SM_BUF;              // pair0 hi
        uint8_t* bl0 = bh0 + BUFBYTES;             // pair0 lo
        #pragma unroll
        for (int w2 = 0; w2 < 2; ++w2) {           // two waves of 8 batched loads
            float4 v[8];
            #pragma unroll
            for (int i = 0; i < 8; ++i)
                v[i] = ok ? src[w2 * 8 + i] : make_float4(0.f, 0.f, 0.f, 0.f);
            #pragma unroll
            for (int i = 0; i < 8; ++i) {
                uint2 p01 = pack2(v[i].x, v[i].y);
                uint2 p23 = pack2(v[i].z, v[i].w);
                uint32_t off = (uint32_t)(r * ROWSTRIDE + (w2 * 8 + i) * 8);
                *(uint2*)(bh0 + off) = make_uint2(p01.x, p23.x);
                *(uint2*)(bl0 + off) = make_uint2(p01.y, p23.y);
            }
        }
    }
    __syncthreads();

    // A-operand ldmatrix row offsets: [slab][tap], rows clamped to [0,127]
    uint32_t aoff[2][3];
    #pragma unroll
    for (int s2 = 0; s2 < 2; ++s2)
        #pragma unroll
        for (int t = 0; t < 3; ++t) {
            int rr = wid * 32 + s2 * 16 + t - 1 + (lane & 15);
            rr = rr < 0 ? 0 : (rr > 127 ? 127 : rr);
            aoff[s2][t] = (uint32_t)(rr * ROWSTRIDE) + ((lane >> 4) * 16);
        }

    #pragma unroll
    for (int L = 0; L < 3; ++L) {
        const int inp = (L == 1) ? 1 : 0;          // L0:p0, L1:p1, L2:p0
        const uint32_t inHi = sbase + SM_BUF + (uint32_t)(inp * 2) * BUFBYTES;
        const uint32_t inLo = inHi + BUFBYTES;
        // per-layer fragment base (uint2 granularity), lane folded in
        const uint2* wf = (const uint2*)g_wfrag + (size_t)(bk * 3 + L) * 6144 + lane;

        // ---- final layer: preload scatter rows + prefetch residual x ----
        long long prow_s[4];
        if (L == 2) {
            #pragma unroll
            for (int s2 = 0; s2 < 2; ++s2)
                #pragma unroll
                for (int rh = 0; rh < 2; ++rh) {
                    const int r = wid * 32 + s2 * 16 + rh * 8 + (lane >> 2);
                    const int gp = ts - 3 + r;
                    const bool ok = (r >= 3) && (r <= 124) && (gp < N_);
                    int gpc = ok ? gp : 0;
                    long long prow = is64 ? pa64[(size_t)b * N_ + gpc]
                                          : (long long)pa32[(size_t)b * N_ + gpc];
                    prow_s[s2 * 2 + rh] = prow;
                    if (ok) {
                        const char* xp = (const char*)(xin + ((size_t)b * N_ + (size_t)prow) * 64)
                                       + (lane & 3) * 64;
                        asm volatile("prefetch.global.L2 [%0];" :: "l"(xp));
                    }
                }
        }

        float d[2][8][4];
        #pragma unroll
        for (int s2 = 0; s2 < 2; ++s2)
            #pragma unroll
            for (int nb = 0; nb < 8; ++nb)
                #pragma unroll
                for (int j = 0; j < 4; ++j) d[s2][nb][j] = 0.f;

        #pragma unroll
        for (int t = 0; t < 3; ++t) {
            #pragma unroll
            for (int kb = 0; kb < 4; ++kb) {
                uint32_t a0[4], a1[4];
                LDSM4(a0, inHi + aoff[0][t] + kb * 32);
                LDSM4(a1, inHi + aoff[1][t] + kb * 32);

                uint2 bh[8];
                #pragma unroll
                for (int nb = 0; nb < 8; ++nb) {       // A_hi * B_hi
                    bh[nb] = __ldg(wf + (size_t)((((t * 2 + 0) * 8 + nb) * 4 + kb) * 32));
                    mma_bf16(d[0][nb], a0, bh[nb].x, bh[nb].y);
                    mma_bf16(d[1][nb], a1, bh[nb].x, bh[nb].y);
                }
                #pragma unroll
                for (int nb = 0; nb < 8; ++nb) {       // A_hi * B_lo
                    uint2 bl = __ldg(wf + (size_t)((((t * 2 + 1) * 8 + nb) * 4 + kb) * 32));
                    mma_bf16(d[0][nb], a0, bl.x, bl.y);
                    mma_bf16(d[1][nb], a1, bl.x, bl.y);
                }
                LDSM4(a0, inLo + aoff[0][t] + kb * 32);
                LDSM4(a1, inLo + aoff[1][t] + kb * 32);
                #pragma unroll
                for (int nb = 0; nb < 8; ++nb) {       // A_lo * B_hi
                    mma_bf16(d[0][nb], a0, bh[nb].x, bh[nb].y);
                    mma_bf16(d[1][nb], a1, bh[nb].x, bh[nb].y);
                }
            }
        }

        // ---- epilogue ----
        const float* bias = (const float*)(smem + SM_BIAS) + L * 64;

        if (L < 2) {
            const int outp = (L == 0) ? 1 : 0;
            uint8_t* oh = smem + SM_BUF + (uint32_t)(outp * 2) * BUFBYTES;
            uint8_t* ol = oh + BUFBYTES;
            #pragma unroll
            for (int s2 = 0; s2 < 2; ++s2) {
                #pragma unroll
                for (int rh = 0; rh < 2; ++rh) {
                    const int r = wid * 32 + s2 * 16 + rh * 8 + (lane >> 2);
                    const int gp = ts - 3 + r;
                    const bool valid = (r >= L + 1) && (r <= 126 - L) && (gp >= 0) && (gp < N_);
                    #pragma unroll
                    for (int nb = 0; nb < 8; ++nb) {
                        const int c0 = nb * 8 + (lane & 3) * 2;
                        float v0 = valid ? fmaxf(d[s2][nb][rh * 2 + 0] + bias[c0], 0.f) : 0.f;
                        float v1 = valid ? fmaxf(d[s2][nb][rh * 2 + 1] + bias[c0 + 1], 0.f) : 0.f;
                        uint2 p = pack2(v0, v1);
                        uint32_t off = (uint32_t)(r * ROWSTRIDE + c0 * 2);
                        *(uint32_t*)(oh + off) = p.x;
                        *(uint32_t*)(ol + off) = p.y;
                    }
                }
            }
            __syncthreads();     // epilogue visible before next layer reads
        } else {
            // residual (prefetched) + ReLU + permuted scatter
            #pragma unroll
            for (int s2 = 0; s2 < 2; ++s2) {
                #pragma unroll
                for (int rh = 0; rh < 2; ++rh) {
                    const int r = wid * 32 + s2 * 16 + rh * 8 + (lane >> 2);
                    const int gp = ts - 3 + r;
                    if (r >= 3 && r <= 124 && gp < N_) {
                        long long prow = prow_s[s2 * 2 + rh];
                        const float* xp = xin + ((size_t)b * N_ + (size_t)prow) * 64;
                        float* op = out + ((size_t)b * N_ + (size_t)prow) * 64;
                        #pragma unroll
                        for (int nb = 0; nb < 8; ++nb) {
                            const int c0 = nb * 8 + (lane & 3) * 2;
                            float2 xv = *(const float2*)(xp + c0);
                            float2 o2;
                            o2.x = fmaxf(xv.x + d[s2][nb][rh * 2 + 0] + bias[c0], 0.f);
                            o2.y = fmaxf(xv.y + d[s2][nb][rh * 2 + 1] + bias[c0 + 1], 0.f);
                            *(float2*)(op + c0) = o2;
                        }
                    }
                }
            }
        }
    }
}

// ---------------------------------------------------------------------------
extern "C" void kernel_launch(void* const* d_in, const int* in_sizes, int n_in,
                              void* d_out, int out_size)
{
    const float* x      = (const float*)d_in[0];
    const void*  pa1    = d_in[1];
    // d_in[2] = idx_re_1 (unused: re ∘ pa = id, scatter uses pa)
    const void*  pa2    = d_in[3];
    // d_in[4] = idx_re_2 (unused)
    const float* conv_w = (const float*)d_in[5];
    const float* bg     = (const float*)d_in[6];
    const float* bb     = (const float*)d_in[7];
    const float* bm     = (const float*)d_in[8];
    const float* bv     = (const float*)d_in[9];
    float* out = (float*)d_out;

    cudaFuncSetAttribute(mc_block_kernel,
                         cudaFuncAttributeMaxDynamicSharedMemorySize, SM_TOTAL);

    void* tmpp = nullptr;
    cudaGetSymbolAddress(&tmpp, g_tmp);

    prep_kernel<<<(73728 + 255) / 256, 256>>>(conv_w, bg, bb, bm, bv, pa1);

    dim3 grid(NTILE, B_);
    mc_block_kernel<<<grid, 128, SM_TOTAL>>>(x, pa1, (float*)tmpp, 0);
    mc_block_kernel<<<grid, 128, SM_TOTAL>>>((const float*)tmpp, pa2, out, 1);
}